// round 5
// baseline (speedup 1.0000x reference)
#include <cuda_runtime.h>
#include <cstdint>

// Problem sizes (fixed by the reference setup_inputs)
#define Bn 16
#define Nn 1024
#define Mn 4096
#define Dd 64

#define IBLK 128                 // DP consumption granularity (rows) == GTI
#define NIB  (Nn / IBLK)         // 8 i-blocks
#define GTI  128                 // GEMM tile rows (i)
#define GTJ  128                 // GEMM tile cols (j)
#define NJT  (Mn / GTJ)          // 32 j-tiles per (b, iblk)
#define KC   16                  // k-chunk

// Static device scratch (allocation anywhere is forbidden).
__device__ float         g_C[67108864];       // [B][N][M] fp32, 256 MB
__device__ unsigned char g_choice[67108864];  // [B] tiled 32x32 choice bytes, 64 MB
__device__ int           g_cnt[Bn * NIB];     // tile-completion counters

__device__ __forceinline__ float finf() { return __int_as_float(0x7f800000); }

// ---- packed f32x2 helpers (sm_103a: 2x fp32 throughput via fma.rn.f32x2) ----
__device__ __forceinline__ unsigned long long pk2(float lo, float hi) {
    unsigned long long r;
    asm("mov.b64 %0, {%1, %2};" : "=l"(r) : "f"(lo), "f"(hi));
    return r;
}
__device__ __forceinline__ void upk2(unsigned long long v, float& lo, float& hi) {
    asm("mov.b64 {%0, %1}, %2;" : "=f"(lo), "=f"(hi) : "l"(v));
}
__device__ __forceinline__ unsigned long long ffma2(unsigned long long a,
                                                    unsigned long long b,
                                                    unsigned long long c) {
    unsigned long long d;
    asm("fma.rn.f32x2 %0, %1, %2, %3;" : "=l"(d) : "l"(a), "l"(b), "l"(c));
    return d;
}

__global__ void zero_cnt_kernel() {
    if (threadIdx.x < Bn * NIB) g_cnt[threadIdx.x] = 0;
}

// ---------------------------------------------------------------------------
// Fused kernel.
//  blocks [0,16):        persistent DP + backtrack CTA for batch b (1024 thr)
//  blocks [16, 16+4096): GEMM tile CTAs (128x128), i-block outermost so C is
//                        produced in DP consumption order.
// ---------------------------------------------------------------------------
__global__ void __launch_bounds__(1024, 1)
fused_kernel(const float* __restrict__ x, const float* __restrict__ y,
             const float* __restrict__ x_t, const float* __restrict__ y_t,
             float* __restrict__ out) {
    __shared__ __align__(16) unsigned char smem_raw[17920];
    const int t = threadIdx.x;
    const float INF = finf();

    if (blockIdx.x >= Bn) {
        // =================== GEMM CTA (128x128 tile, 4x4 per thread) ========
        float* xs  = (float*)smem_raw;           // [KC][GTI+4]
        float* ys  = xs + KC * (GTI + 4);        // [KC][GTJ+4]
        float* x2s = ys + KC * (GTJ + 4);        // [GTI]
        float* y2s = x2s + GTI;                  // [GTJ]

        int gid  = blockIdx.x - Bn;
        int iblk = gid >> 9;                     // 0..7  (outermost -> in-order)
        int rem  = gid & 511;
        int b    = rem >> 5;                     // 0..15
        int jblk = rem & 31;                     // 0..31
        int i0 = iblk * GTI, j0 = jblk * GTJ;

        const int c4 = (t & 31) * 4;             // cols c4..c4+3
        const int r4 = (t >> 5) * 4;             // rows r4..r4+3

        unsigned long long acc[4][2];
#pragma unroll
        for (int r = 0; r < 4; r++) { acc[r][0] = 0ull; acc[r][1] = 0ull; }

        float x2a = 0.f, y2a = 0.f;

        for (int kc = 0; kc < Dd; kc += KC) {
            // load k-chunk: threads [0,512) load x tile, [512,1024) load y tile
            if (t < 512) {                       // 128 rows x 4 float4
                int row = t >> 2, cc4 = (t & 3) * 4;
                float4 v = *reinterpret_cast<const float4*>(
                    x + ((size_t)b * Nn + i0 + row) * Dd + kc + cc4);
                xs[(cc4 + 0) * (GTI + 4) + row] = v.x;
                xs[(cc4 + 1) * (GTI + 4) + row] = v.y;
                xs[(cc4 + 2) * (GTI + 4) + row] = v.z;
                xs[(cc4 + 3) * (GTI + 4) + row] = v.w;
            } else {
                int u = t - 512;
                int row = u >> 2, cc4 = (u & 3) * 4;
                float4 v = *reinterpret_cast<const float4*>(
                    y + ((size_t)b * Mn + j0 + row) * Dd + kc + cc4);
                ys[(cc4 + 0) * (GTJ + 4) + row] = v.x;
                ys[(cc4 + 1) * (GTJ + 4) + row] = v.y;
                ys[(cc4 + 2) * (GTJ + 4) + row] = v.z;
                ys[(cc4 + 3) * (GTJ + 4) + row] = v.w;
            }
            __syncthreads();

            // norm accumulation (register-resident across chunks)
            if (t < GTI) {
#pragma unroll
                for (int k = 0; k < KC; k++) {
                    float v = xs[k * (GTI + 4) + t];
                    x2a = fmaf(v, v, x2a);
                }
            } else if (t < GTI + GTJ) {
                int j = t - GTI;
#pragma unroll
                for (int k = 0; k < KC; k++) {
                    float v = ys[k * (GTJ + 4) + j];
                    y2a = fmaf(v, v, y2a);
                }
            }

            // inner product: rows r4..r4+3 (broadcast), cols c4..c4+3 (dense)
#pragma unroll
            for (int k = 0; k < KC; k++) {
                float4 av = *reinterpret_cast<const float4*>(&xs[k * (GTI + 4) + r4]);
                float4 b0 = *reinterpret_cast<const float4*>(&ys[k * (GTJ + 4) + c4]);
                unsigned long long b01 = pk2(b0.x, b0.y);
                unsigned long long b23 = pk2(b0.z, b0.w);
                unsigned long long a0 = pk2(av.x, av.x);
                unsigned long long a1 = pk2(av.y, av.y);
                unsigned long long a2 = pk2(av.z, av.z);
                unsigned long long a3 = pk2(av.w, av.w);
                acc[0][0] = ffma2(a0, b01, acc[0][0]); acc[0][1] = ffma2(a0, b23, acc[0][1]);
                acc[1][0] = ffma2(a1, b01, acc[1][0]); acc[1][1] = ffma2(a1, b23, acc[1][1]);
                acc[2][0] = ffma2(a2, b01, acc[2][0]); acc[2][1] = ffma2(a2, b23, acc[2][1]);
                acc[3][0] = ffma2(a3, b01, acc[3][0]); acc[3][1] = ffma2(a3, b23, acc[3][1]);
            }
            __syncthreads();
        }

        if (t < GTI) x2s[t] = x2a;
        else if (t < GTI + GTJ) y2s[t - GTI] = y2a;
        __syncthreads();

        // epilogue: C = x2 + y2 - 2*dot
#pragma unroll
        for (int r = 0; r < 4; r++) {
            float xr = x2s[r4 + r];
            float a0, a1, a2, a3;
            upk2(acc[r][0], a0, a1); upk2(acc[r][1], a2, a3);
            float4 o;
            o.x = xr + y2s[c4 + 0] - 2.f * a0;
            o.y = xr + y2s[c4 + 1] - 2.f * a1;
            o.z = xr + y2s[c4 + 2] - 2.f * a2;
            o.w = xr + y2s[c4 + 3] - 2.f * a3;
            *reinterpret_cast<float4*>(
                g_C + ((size_t)b * Nn + i0 + r4 + r) * Mn + j0 + c4) = o;
        }

        // publish tile completion (release; canonical fence+bar+atomic pattern)
        __threadfence();
        __syncthreads();
        if (t == 0) atomicAdd(&g_cnt[b * NIB + iblk], 1);
        return;
    }

    // =================== DP + backtrack CTA (batch b) ===================
    float* wSb  = (float*)smem_raw;                      // [2][32]
    float* wMb  = wSb + 64;                              // [2][32]
    volatile int* sCtl = (volatile int*)(wMb + 64);      // [band, j]
    float* sv = (float*)(wMb + 64 + 4);                  // [1024]
    int*   si = (int*)(sv + 1024);                       // [1024]

    const int b = blockIdx.x;
    const int lane = t & 31, wid = t >> 5;
    const float* Cb = g_C + (size_t)b * Nn * Mn;
    unsigned char* chb = g_choice + (size_t)b * Nn * Mn;
    const int j4 = t * 4;

    // wait for i-block 0 of this batch (acquire)
    if (t == 0) {
        while (atomicAdd(&g_cnt[b * NIB + 0], 0) < NJT) __nanosleep(200);
        __threadfence();
    }
    __syncthreads();

    // Row 0: D = C (free start anywhere in y). DP state in registers:
    // pD0..3 = D[i-1] for own cols; carry = D[i-1][4t-1] (INF for t==0).
    float4 cc0 = *reinterpret_cast<const float4*>(Cb + j4);
    float pD0 = cc0.x, pD1 = cc0.y, pD2 = cc0.z, pD3 = cc0.w;
    float carry = (t == 0) ? INF : Cb[j4 - 1];

    // two-row-ahead prefetch pipeline (load-to-use ~2 rows > DRAM latency)
    float4 cnA = *reinterpret_cast<const float4*>(Cb + (size_t)1 * Mn + j4);
    float4 cnB = *reinterpret_cast<const float4*>(Cb + (size_t)2 * Mn + j4);

    for (int i = 1; i < Nn; i++) {
        float4 cc;
        if ((i & (IBLK - 1)) == 0) {            // uniform condition
            if (t == 0) {
                while (atomicAdd(&g_cnt[b * NIB + (i >> 7)], 0) < NJT) __nanosleep(200);
                __threadfence();
            }
            __syncthreads();
            // refill the pipeline inside the freshly-ready block
            cc  = *reinterpret_cast<const float4*>(Cb + (size_t)i * Mn + j4);
            cnA = *reinterpret_cast<const float4*>(Cb + (size_t)(i + 1) * Mn + j4);
            cnB = *reinterpret_cast<const float4*>(Cb + (size_t)(i + 2) * Mn + j4);
        } else {
            cc = cnA; cnA = cnB;
            int nf = i + 2;
            if (nf < Nn && (i & (IBLK - 1)) <= IBLK - 3)
                cnB = *reinterpret_cast<const float4*>(Cb + (size_t)nf * Mn + j4);
        }

        const float up0 = pD0, up1 = pD1, up2 = pD2, up3 = pD3, dg0 = carry;

        float a0 = fminf(up0, dg0) + cc.x;
        float a1 = fminf(up1, up0) + cc.y;
        float a2 = fminf(up2, up1) + cc.z;
        float a3 = fminf(up3, up2) + cc.w;

        float s0 = cc.x, s1 = s0 + cc.y, s2 = s1 + cc.z, s3 = s2 + cc.w;
        float m0 = a0 - s0;
        float m1 = fminf(m0, a1 - s1);
        float m2 = fminf(m1, a2 - s2);
        float m3 = fminf(m2, a3 - s3);

        // warp-level inclusive pair scan: (s,m) op (s',m') = (s+s', min(m, m'-s))
        float S = s3, Mv = m3;
#pragma unroll
        for (int d = 1; d < 32; d <<= 1) {
            float so = __shfl_up_sync(0xffffffffu, S, d);
            float mo = __shfl_up_sync(0xffffffffu, Mv, d);
            if (lane >= d) { Mv = fminf(mo, Mv - so); S = S + so; }
        }
        float sE = __shfl_up_sync(0xffffffffu, S, 1);
        float mE = __shfl_up_sync(0xffffffffu, Mv, 1);
        if (lane == 0) { sE = 0.f; mE = INF; }

        const int par = (i & 1) * 32;
        if (lane == 31) { wSb[par + wid] = S; wMb[par + wid] = Mv; }
        __syncthreads();   // the ONLY barrier per row

        // redundant level-2 scan in every warp (no second barrier needed)
        float Sw = wSb[par + lane], Mw = wMb[par + lane];
#pragma unroll
        for (int d = 1; d < 32; d <<= 1) {
            float so = __shfl_up_sync(0xffffffffu, Sw, d);
            float mo = __shfl_up_sync(0xffffffffu, Mw, d);
            if (lane >= d) { Mw = fminf(mo, Mw - so); Sw = Sw + so; }
        }
        float Sg = 0.f, Mg = INF;
        if (wid > 0) {
            Sg = __shfl_sync(0xffffffffu, Sw, wid - 1);
            Mg = __shfl_sync(0xffffffffu, Mw, wid - 1);
        }
        float offS = Sg + sE;               // exclusive prefix sum before this thread
        float PexM = fminf(Mg, mE - Sg);    // exclusive prefix min of (a - S)

        float D0 = offS + s0 + fminf(PexM, m0 - offS);
        float D1 = offS + s1 + fminf(PexM, m1 - offS);
        float D2 = offS + s2 + fminf(PexM, m2 - offS);
        float D3 = offS + s3 + fminf(PexM, m3 - offS);

        // D[i][4t-1] == offS + PexM (INF for t==0)
        float dl0 = offS + PexM;

        // choice codes: 0=diag, 1=up, 2=left (tie priority diag > up > left)
        unsigned char q0 = (dg0 <= up0 && dg0 <= dl0) ? 0 : ((up0 <= dl0) ? 1 : 2);
        unsigned char q1 = (up0 <= up1 && up0 <= D0)  ? 0 : ((up1 <= D0)  ? 1 : 2);
        unsigned char q2 = (up1 <= up2 && up1 <= D1)  ? 0 : ((up2 <= D1)  ? 1 : 2);
        unsigned char q3 = (up2 <= up3 && up2 <= D2)  ? 0 : ((up3 <= D2)  ? 1 : 2);

        size_t caddr = (size_t)((i >> 5) * (Mn / 32) + (j4 >> 5)) * 1024
                     + (size_t)(i & 31) * 32 + (j4 & 31);
        *reinterpret_cast<uchar4*>(chb + caddr) = make_uchar4(q0, q1, q2, q3);

        pD0 = D0; pD1 = D1; pD2 = D2; pD3 = D3;
        carry = dl0;
    }

    float* w_ts = out + Bn;
    float* w_vs = out + Bn + Bn * Nn;
    for (int ii = t; ii < Nn; ii += 1024) w_ts[b * Nn + ii] = x_t[b * Nn + ii];

    // argmin (first occurrence) over last row, from registers
    float bv = pD0; int bj = j4;
    if (pD1 < bv) { bv = pD1; bj = j4 + 1; }
    if (pD2 < bv) { bv = pD2; bj = j4 + 2; }
    if (pD3 < bv) { bv = pD3; bj = j4 + 3; }
    sv[t] = bv; si[t] = bj;
    __syncthreads();
    for (int s = 512; s > 0; s >>= 1) {
        if (t < s) {
            float v2 = sv[t + s]; int j2 = si[t + s];
            if (v2 < sv[t] || (v2 == sv[t] && j2 < si[t])) { sv[t] = v2; si[t] = j2; }
        }
        __syncthreads();
    }
    if (t == 0) { sCtl[0] = (Nn / 32) - 1; sCtl[1] = si[0]; }
    __syncthreads();

    if (t == 0) {
        // serial path walker
        out[b] = sv[0];
        int i = Nn - 1, j = si[0];
        int lastBand = (Nn / 32) - 1;
        w_vs[b * Nn + i] = y_t[b * Mn + j];
        while (i > 0) {
            unsigned char ch = chb[(size_t)((i >> 5) * (Mn / 32) + (j >> 5)) * 1024
                                   + (size_t)(i & 31) * 32 + (j & 31)];
            if (ch == 0)      { --i; --j; w_vs[b * Nn + i] = y_t[b * Mn + j]; }
            else if (ch == 1) { --i;      w_vs[b * Nn + i] = y_t[b * Mn + j]; }
            else              { --j; }
            int nb = i >> 5;
            if (nb != lastBand) { lastBand = nb; sCtl[0] = nb; sCtl[1] = j; }
        }
        sCtl[0] = -1;
    } else if (t >= 64) {
        // band pre-warmers: pull a j-window of band tb into L1 ahead of walker
        const int wt = t - 64;                   // 0..959
        int sink = 0;
        for (int tb = (Nn / 32) - 1; tb >= 0; --tb) {
            for (;;) {
                int sb = sCtl[0];
                if (sb < 0) goto warm_done;
                if (sb <= tb + 1) break;
                __nanosleep(200);
            }
            int jc = sCtl[1];
            int jtl = (jc >> 5) - 20; if (jtl < 0) jtl = 0;
            int jth = (jc >> 5) + 1;  if (jth > (Mn / 32) - 1) jth = (Mn / 32) - 1;
            int nsec = (jth - jtl + 1) * 32;     // 32-byte sectors
            const unsigned char* base = chb + (size_t)tb * (Mn / 32) * 1024;
            for (int s2 = wt; s2 < nsec; s2 += 960)
                sink += base[(size_t)(jtl + (s2 >> 5)) * 1024 + (s2 & 31) * 32];
        }
    warm_done:
        asm volatile("" :: "r"(sink));
    }
}

// ---------------------------------------------------------------------------
extern "C" void kernel_launch(void* const* d_in, const int* in_sizes, int n_in,
                              void* d_out, int out_size) {
    const float* x   = (const float*)d_in[0];   // [16,1024,64]
    const float* y   = (const float*)d_in[1];   // [16,4096,64]
    const float* x_t = (const float*)d_in[2];   // [16,1024]
    const float* y_t = (const float*)d_in[3];   // [16,4096]
    float* out = (float*)d_out;                 // 16 + 16384 + 16384 floats

    zero_cnt_kernel<<<1, 128>>>();
    fused_kernel<<<Bn + Bn * NIB * NJT, 1024>>>(x, y, x_t, y_t, out);
}

// round 9
// speedup vs baseline: 1.0382x; 1.0382x over previous
#include <cuda_runtime.h>
#include <cstdint>

// Problem sizes (fixed by the reference setup_inputs)
#define Bn 16
#define Nn 1024
#define Mn 4096
#define Dd 64

#define IBLK 128                 // DP consumption granularity (rows) == GTI
#define NIB  (Nn / IBLK)         // 8 i-blocks
#define GTI  128                 // GEMM tile rows (i)
#define GTJ  128                 // GEMM tile cols (j)
#define NJT  (Mn / GTJ)          // 32 j-tiles per (b, iblk)
#define KC   16                  // k-chunk
#define NBAND (Nn / 32)          // 32 backtrack bands

// Static device scratch (allocation anywhere is forbidden).
__device__ float          g_C[67108864];       // [B][N][M] fp32, 256 MB
__device__ unsigned char  g_choice[67108864];  // [B] tiled 32x32 choice bytes, 64 MB
__device__ int            g_cnt[Bn * NIB];     // tile-completion counters
__device__ int            g_j0[Bn];            // per-batch argmin column of last row
__device__ unsigned short g_exitJ[Bn][NBAND][Mn]; // band exit columns, 4 MB

__device__ __forceinline__ float finf() { return __int_as_float(0x7f800000); }

// ---- packed f32x2 helpers (sm_103a: 2x fp32 throughput via fma.rn.f32x2) ----
__device__ __forceinline__ unsigned long long pk2(float lo, float hi) {
    unsigned long long r;
    asm("mov.b64 %0, {%1, %2};" : "=l"(r) : "f"(lo), "f"(hi));
    return r;
}
__device__ __forceinline__ void upk2(unsigned long long v, float& lo, float& hi) {
    asm("mov.b64 {%0, %1}, %2;" : "=f"(lo), "=f"(hi) : "l"(v));
}
__device__ __forceinline__ unsigned long long ffma2(unsigned long long a,
                                                    unsigned long long b,
                                                    unsigned long long c) {
    unsigned long long d;
    asm("fma.rn.f32x2 %0, %1, %2, %3;" : "=l"(d) : "l"(a), "l"(b), "l"(c));
    return d;
}

// tiled 32x32 choice address
__device__ __forceinline__ size_t chaddr(int i, int j) {
    return (size_t)((i >> 5) * (Mn / 32) + (j >> 5)) * 1024
         + (size_t)(i & 31) * 32 + (j & 31);
}

__global__ void zero_cnt_kernel() {
    if (threadIdx.x < Bn * NIB) g_cnt[threadIdx.x] = 0;
}

// ---------------------------------------------------------------------------
// Fused kernel.
//  blocks [0,16):        persistent DP CTA for batch b (1024 threads)
//  blocks [16, 16+4096): GEMM tile CTAs (128x128), i-block outermost so C is
//                        produced in DP consumption order.
// ---------------------------------------------------------------------------
__global__ void __launch_bounds__(1024, 1)
fused_kernel(const float* __restrict__ x, const float* __restrict__ y,
             const float* __restrict__ x_t, float* __restrict__ out) {
    __shared__ __align__(16) unsigned char smem_raw[17920];
    const int t = threadIdx.x;
    const float INF = finf();

    if (blockIdx.x >= Bn) {
        // =================== GEMM CTA (128x128 tile, 4x4 per thread) ========
        float* xs  = (float*)smem_raw;           // [KC][GTI+4]
        float* ys  = xs + KC * (GTI + 4);        // [KC][GTJ+4]
        float* x2s = ys + KC * (GTJ + 4);        // [GTI]
        float* y2s = x2s + GTI;                  // [GTJ]

        int gid  = blockIdx.x - Bn;
        int iblk = gid >> 9;                     // 0..7  (outermost -> in-order)
        int rem  = gid & 511;
        int b    = rem >> 5;                     // 0..15
        int jblk = rem & 31;                     // 0..31
        int i0 = iblk * GTI, j0 = jblk * GTJ;

        const int c4 = (t & 31) * 4;             // cols c4..c4+3
        const int r4 = (t >> 5) * 4;             // rows r4..r4+3

        unsigned long long acc[4][2];
#pragma unroll
        for (int r = 0; r < 4; r++) { acc[r][0] = 0ull; acc[r][1] = 0ull; }

        float x2a = 0.f, y2a = 0.f;

        for (int kc = 0; kc < Dd; kc += KC) {
            if (t < 512) {                       // x tile: 128 rows x 4 float4
                int row = t >> 2, cc4 = (t & 3) * 4;
                float4 v = *reinterpret_cast<const float4*>(
                    x + ((size_t)b * Nn + i0 + row) * Dd + kc + cc4);
                xs[(cc4 + 0) * (GTI + 4) + row] = v.x;
                xs[(cc4 + 1) * (GTI + 4) + row] = v.y;
                xs[(cc4 + 2) * (GTI + 4) + row] = v.z;
                xs[(cc4 + 3) * (GTI + 4) + row] = v.w;
            } else {                             // y tile
                int u = t - 512;
                int row = u >> 2, cc4 = (u & 3) * 4;
                float4 v = *reinterpret_cast<const float4*>(
                    y + ((size_t)b * Mn + j0 + row) * Dd + kc + cc4);
                ys[(cc4 + 0) * (GTJ + 4) + row] = v.x;
                ys[(cc4 + 1) * (GTJ + 4) + row] = v.y;
                ys[(cc4 + 2) * (GTJ + 4) + row] = v.z;
                ys[(cc4 + 3) * (GTJ + 4) + row] = v.w;
            }
            __syncthreads();

            if (t < GTI) {
#pragma unroll
                for (int k = 0; k < KC; k++) {
                    float v = xs[k * (GTI + 4) + t];
                    x2a = fmaf(v, v, x2a);
                }
            } else if (t < GTI + GTJ) {
                int j = t - GTI;
#pragma unroll
                for (int k = 0; k < KC; k++) {
                    float v = ys[k * (GTJ + 4) + j];
                    y2a = fmaf(v, v, y2a);
                }
            }

#pragma unroll
            for (int k = 0; k < KC; k++) {
                float4 av = *reinterpret_cast<const float4*>(&xs[k * (GTI + 4) + r4]);
                float4 b0 = *reinterpret_cast<const float4*>(&ys[k * (GTJ + 4) + c4]);
                unsigned long long b01 = pk2(b0.x, b0.y);
                unsigned long long b23 = pk2(b0.z, b0.w);
                unsigned long long a0 = pk2(av.x, av.x);
                unsigned long long a1 = pk2(av.y, av.y);
                unsigned long long a2 = pk2(av.z, av.z);
                unsigned long long a3 = pk2(av.w, av.w);
                acc[0][0] = ffma2(a0, b01, acc[0][0]); acc[0][1] = ffma2(a0, b23, acc[0][1]);
                acc[1][0] = ffma2(a1, b01, acc[1][0]); acc[1][1] = ffma2(a1, b23, acc[1][1]);
                acc[2][0] = ffma2(a2, b01, acc[2][0]); acc[2][1] = ffma2(a2, b23, acc[2][1]);
                acc[3][0] = ffma2(a3, b01, acc[3][0]); acc[3][1] = ffma2(a3, b23, acc[3][1]);
            }
            __syncthreads();
        }

        if (t < GTI) x2s[t] = x2a;
        else if (t < GTI + GTJ) y2s[t - GTI] = y2a;
        __syncthreads();

#pragma unroll
        for (int r = 0; r < 4; r++) {
            float xr = x2s[r4 + r];
            float a0, a1, a2, a3;
            upk2(acc[r][0], a0, a1); upk2(acc[r][1], a2, a3);
            float4 o;
            o.x = xr + y2s[c4 + 0] - 2.f * a0;
            o.y = xr + y2s[c4 + 1] - 2.f * a1;
            o.z = xr + y2s[c4 + 2] - 2.f * a2;
            o.w = xr + y2s[c4 + 3] - 2.f * a3;
            *reinterpret_cast<float4*>(
                g_C + ((size_t)b * Nn + i0 + r4 + r) * Mn + j0 + c4) = o;
        }

        // publish tile completion (release)
        __threadfence();
        __syncthreads();
        if (t == 0) atomicAdd(&g_cnt[b * NIB + iblk], 1);
        return;
    }

    // =================== DP CTA (batch b) ===================
    float* wSb  = (float*)smem_raw;                      // [2][32]
    float* wMb  = wSb + 64;                              // [2][32]
    float* sv   = wMb + 64 + 4;                          // [1024]
    int*   si   = (int*)(sv + 1024);                     // [1024]

    const int b = blockIdx.x;
    const int lane = t & 31, wid = t >> 5;
    const float* Cb = g_C + (size_t)b * Nn * Mn;
    unsigned char* chb = g_choice + (size_t)b * Nn * Mn;
    const int j4 = t * 4;

    // wait for i-block 0 of this batch (acquire)
    if (t == 0) {
        while (atomicAdd(&g_cnt[b * NIB + 0], 0) < NJT) __nanosleep(200);
        __threadfence();
    }
    __syncthreads();

    // Row 0: D = C. DP state in registers:
    // pD0..3 = D[i-1] own cols; carry = D[i-1][4t-1] (INF for t==0).
    float4 cc0 = *reinterpret_cast<const float4*>(Cb + j4);
    float pD0 = cc0.x, pD1 = cc0.y, pD2 = cc0.z, pD3 = cc0.w;
    float carry = (t == 0) ? INF : Cb[j4 - 1];

    // two-row-ahead prefetch pipeline
    float4 cnA = *reinterpret_cast<const float4*>(Cb + (size_t)1 * Mn + j4);
    float4 cnB = *reinterpret_cast<const float4*>(Cb + (size_t)2 * Mn + j4);

    for (int i = 1; i < Nn; i++) {
        float4 cc;
        if ((i & (IBLK - 1)) == 0) {            // uniform condition
            if (t == 0) {
                while (atomicAdd(&g_cnt[b * NIB + (i >> 7)], 0) < NJT) __nanosleep(200);
                __threadfence();
            }
            __syncthreads();
            cc  = *reinterpret_cast<const float4*>(Cb + (size_t)i * Mn + j4);
            cnA = *reinterpret_cast<const float4*>(Cb + (size_t)(i + 1) * Mn + j4);
            cnB = *reinterpret_cast<const float4*>(Cb + (size_t)(i + 2) * Mn + j4);
        } else {
            cc = cnA; cnA = cnB;
            int nf = i + 2;
            if (nf < Nn && (i & (IBLK - 1)) <= IBLK - 3)
                cnB = *reinterpret_cast<const float4*>(Cb + (size_t)nf * Mn + j4);
        }

        const float up0 = pD0, up1 = pD1, up2 = pD2, up3 = pD3, dg0 = carry;

        float a0 = fminf(up0, dg0) + cc.x;
        float a1 = fminf(up1, up0) + cc.y;
        float a2 = fminf(up2, up1) + cc.z;
        float a3 = fminf(up3, up2) + cc.w;

        float s0 = cc.x, s1 = s0 + cc.y, s2 = s1 + cc.z, s3 = s2 + cc.w;
        float m0 = a0 - s0;
        float m1 = fminf(m0, a1 - s1);
        float m2 = fminf(m1, a2 - s2);
        float m3 = fminf(m2, a3 - s3);

        // warp-level inclusive pair scan: (s,m) op (s',m') = (s+s', min(m, m'-s))
        float S = s3, Mv = m3;
#pragma unroll
        for (int d = 1; d < 32; d <<= 1) {
            float so = __shfl_up_sync(0xffffffffu, S, d);
            float mo = __shfl_up_sync(0xffffffffu, Mv, d);
            if (lane >= d) { Mv = fminf(mo, Mv - so); S = S + so; }
        }
        float sE = __shfl_up_sync(0xffffffffu, S, 1);
        float mE = __shfl_up_sync(0xffffffffu, Mv, 1);
        if (lane == 0) { sE = 0.f; mE = INF; }

        const int par = (i & 1) * 32;
        if (lane == 31) { wSb[par + wid] = S; wMb[par + wid] = Mv; }
        __syncthreads();   // the ONLY barrier per row

        // redundant level-2 scan in every warp
        float Sw = wSb[par + lane], Mw = wMb[par + lane];
#pragma unroll
        for (int d = 1; d < 32; d <<= 1) {
            float so = __shfl_up_sync(0xffffffffu, Sw, d);
            float mo = __shfl_up_sync(0xffffffffu, Mw, d);
            if (lane >= d) { Mw = fminf(mo, Mw - so); Sw = Sw + so; }
        }
        float Sg = 0.f, Mg = INF;
        if (wid > 0) {
            Sg = __shfl_sync(0xffffffffu, Sw, wid - 1);
            Mg = __shfl_sync(0xffffffffu, Mw, wid - 1);
        }
        float offS = Sg + sE;               // exclusive prefix sum
        float PexM = fminf(Mg, mE - Sg);    // exclusive prefix min of (a - S)

        float D0 = offS + s0 + fminf(PexM, m0 - offS);
        float D1 = offS + s1 + fminf(PexM, m1 - offS);
        float D2 = offS + s2 + fminf(PexM, m2 - offS);
        float D3 = offS + s3 + fminf(PexM, m3 - offS);

        float dl0 = offS + PexM;            // == D[i][4t-1] (INF for t==0)

        // choice codes: 0=diag, 1=up, 2=left (tie priority diag > up > left)
        unsigned char q0 = (dg0 <= up0 && dg0 <= dl0) ? 0 : ((up0 <= dl0) ? 1 : 2);
        unsigned char q1 = (up0 <= up1 && up0 <= D0)  ? 0 : ((up1 <= D0)  ? 1 : 2);
        unsigned char q2 = (up1 <= up2 && up1 <= D1)  ? 0 : ((up2 <= D1)  ? 1 : 2);
        unsigned char q3 = (up2 <= up3 && up2 <= D2)  ? 0 : ((up3 <= D2)  ? 1 : 2);

        *reinterpret_cast<uchar4*>(chb + chaddr(i, j4)) = make_uchar4(q0, q1, q2, q3);

        pD0 = D0; pD1 = D1; pD2 = D2; pD3 = D3;
        carry = dl0;
    }

    float* w_ts = out + Bn;
    for (int ii = t; ii < Nn; ii += 1024) w_ts[b * Nn + ii] = x_t[b * Nn + ii];

    // argmin (first occurrence) over last row, from registers
    float bv = pD0; int bj = j4;
    if (pD1 < bv) { bv = pD1; bj = j4 + 1; }
    if (pD2 < bv) { bv = pD2; bj = j4 + 2; }
    if (pD3 < bv) { bv = pD3; bj = j4 + 3; }
    sv[t] = bv; si[t] = bj;
    __syncthreads();
    for (int s = 512; s > 0; s >>= 1) {
        if (t < s) {
            float v2 = sv[t + s]; int j2 = si[t + s];
            if (v2 < sv[t] || (v2 == sv[t] && j2 < si[t])) { sv[t] = v2; si[t] = j2; }
        }
        __syncthreads();
    }
    if (t == 0) { out[b] = sv[0]; g_j0[b] = si[0]; }
}

// ---------------------------------------------------------------------------
// Band-parallel backtrack precompute: for every (batch, band tb in [1,31],
// entry column j) walk the 32-row segment; record exit column (the column at
// row 32*tb - 1 if the true path enters this band at column j).
// ---------------------------------------------------------------------------
__global__ void __launch_bounds__(256) bandwalk_kernel() {
    const int tb = blockIdx.x + 1;               // 1..31
    const int b  = blockIdx.y;
    const unsigned char* chb = g_choice + (size_t)b * Nn * Mn;
    const int iTop  = tb * 32 + 31;
    const int iStop = tb * 32 - 1;               // walk while i > iStop

#pragma unroll
    for (int k = 0; k < Mn / 256; k++) {
        int j = threadIdx.x + k * 256;
        int jin = j;
        int i = iTop;
        while (i > iStop) {
            unsigned char ch = __ldg(chb + chaddr(i, j));
            if (ch == 0)      { --i; --j; }
            else if (ch == 1) { --i; }
            else              { --j; }
        }
        g_exitJ[b][tb][jin] = (unsigned short)j;
    }
}

// ---------------------------------------------------------------------------
// Finalize: per batch, chain band entry columns through the exit table, then
// 32 parallel segment re-walks emit w_vs.
// ---------------------------------------------------------------------------
__global__ void __launch_bounds__(64) finalize_kernel(const float* __restrict__ y_t,
                                                      float* __restrict__ out) {
    __shared__ int entry[NBAND];
    const int b = blockIdx.x, t = threadIdx.x;
    float* w_vs = out + Bn + Bn * Nn;
    const float* ytb = y_t + (size_t)b * Mn;
    const unsigned char* chb = g_choice + (size_t)b * Nn * Mn;

    if (t == 0) {
        int j = g_j0[b];
        w_vs[b * Nn + (Nn - 1)] = ytb[j];        // row 1023 entry
        entry[NBAND - 1] = j;
        for (int tb = NBAND - 1; tb >= 1; --tb) {
            j = g_exitJ[b][tb][j];
            entry[tb - 1] = j;
        }
    }
    __syncthreads();

    if (t < NBAND) {
        const int tb = t;
        int i = tb * 32 + 31;
        int j = entry[tb];
        const int iStop = (tb == 0) ? 0 : (tb * 32 - 1);
        while (i > iStop) {
            unsigned char ch = __ldg(chb + chaddr(i, j));
            if (ch == 2) { --j; }
            else {
                if (ch == 0) --j;
                --i;
                w_vs[b * Nn + i] = ytb[j];
            }
        }
    }
}

// ---------------------------------------------------------------------------
extern "C" void kernel_launch(void* const* d_in, const int* in_sizes, int n_in,
                              void* d_out, int out_size) {
    const float* x   = (const float*)d_in[0];   // [16,1024,64]
    const float* y   = (const float*)d_in[1];   // [16,4096,64]
    const float* x_t = (const float*)d_in[2];   // [16,1024]
    const float* y_t = (const float*)d_in[3];   // [16,4096]
    float* out = (float*)d_out;                 // 16 + 16384 + 16384 floats

    zero_cnt_kernel<<<1, 128>>>();
    fused_kernel<<<Bn + Bn * NIB * NJT, 1024>>>(x, y, x_t, out);
    bandwalk_kernel<<<dim3(NBAND - 1, Bn), 256>>>();
    finalize_kernel<<<Bn, 64>>>(y_t, out);
}